// round 2
// baseline (speedup 1.0000x reference)
#include <cuda_runtime.h>
#include <math.h>

#define L_SEQ   1024
#define DMODEL  1024
#define N_BATCH 4
#define N_HEADS 16
#define DEPTH   64
#define M_TOT   (N_BATCH * L_SEQ)   // 4096

// Scratch (device globals: no allocation allowed)
__device__ float g_Q[N_BATCH * N_HEADS * L_SEQ * DEPTH];   // [n][h][l][d]
__device__ float g_K[N_BATCH * N_HEADS * L_SEQ * DEPTH];
__device__ float g_V[N_BATCH * N_HEADS * L_SEQ * DEPTH];
__device__ float g_ctx[M_TOT * DMODEL];                    // [n*L + l][h*64+d]

// ---------------------------------------------------------------------------
// Fused QKV projection GEMM.
// C_z[M=4096, N=1024] = A_z[4096,1024] @ B_z[1024,1024] + bias_z, z = 0,1,2
// 128x128 block, BK=8, 256 threads, 8x8 per-thread microtile.
// Output written in [n][h][l][d] split-head scratch layout.
// ---------------------------------------------------------------------------
__global__ __launch_bounds__(256) void qkv_gemm(
    const float* __restrict__ Aq, const float* __restrict__ Ak,
    const float* __restrict__ Av,
    const float* __restrict__ Bq, const float* __restrict__ Bk,
    const float* __restrict__ Bv,
    const float* __restrict__ bq, const float* __restrict__ bk,
    const float* __restrict__ bv,
    float* __restrict__ Cq, float* __restrict__ Ck, float* __restrict__ Cv)
{
    __shared__ float As[8][132];   // transposed: As[k][m]
    __shared__ float Bs[8][132];   // Bs[k][n]

    const int z = blockIdx.z;
    const float* A    = (z == 0) ? Aq : (z == 1) ? Ak : Av;
    const float* B    = (z == 0) ? Bq : (z == 1) ? Bk : Bv;
    const float* bias = (z == 0) ? bq : (z == 1) ? bk : bv;
    float*       C    = (z == 0) ? Cq : (z == 1) ? Ck : Cv;

    const int tid = threadIdx.x;
    const int bx = blockIdx.x;     // N / 128 = 8
    const int by = blockIdx.y;     // M / 128 = 32
    const int tx = tid & 15;
    const int ty = tid >> 4;

    const int aRow = tid >> 1;           // 0..127
    const int aCol = (tid & 1) << 2;     // 0 or 4
    const int bRow = tid >> 5;           // 0..7
    const int bCol = (tid & 31) << 2;    // 0..124

    const float* Ap = A + (size_t)(by * 128 + aRow) * 1024 + aCol;
    const float* Bp = B + (size_t)bRow * 1024 + bx * 128 + bCol;

    float acc[8][8];
#pragma unroll
    for (int i = 0; i < 8; i++)
#pragma unroll
        for (int j = 0; j < 8; j++) acc[i][j] = 0.f;

    for (int k0 = 0; k0 < 1024; k0 += 8) {
        float4 av = *(const float4*)(Ap + k0);
        float4 bv4 = *(const float4*)(Bp + (size_t)k0 * 1024);
        As[aCol + 0][aRow] = av.x;
        As[aCol + 1][aRow] = av.y;
        As[aCol + 2][aRow] = av.z;
        As[aCol + 3][aRow] = av.w;
        *(float4*)&Bs[bRow][bCol] = bv4;
        __syncthreads();

#pragma unroll
        for (int k = 0; k < 8; k++) {
            float a[8], b[8];
#pragma unroll
            for (int i = 0; i < 8; i++) a[i] = As[k][ty * 8 + i];
#pragma unroll
            for (int j = 0; j < 8; j++) b[j] = Bs[k][tx * 8 + j];
#pragma unroll
            for (int i = 0; i < 8; i++)
#pragma unroll
                for (int j = 0; j < 8; j++) acc[i][j] += a[i] * b[j];
        }
        __syncthreads();
    }

    const int m0 = by * 128 + ty * 8;
    const int n0 = bx * 128 + tx * 8;
#pragma unroll
    for (int i = 0; i < 8; i++) {
        const int m = m0 + i;
        const int batch = m >> 10, l = m & 1023;
#pragma unroll
        for (int j = 0; j < 8; j++) {
            const int n = n0 + j;
            const float v = acc[i][j] + __ldg(&bias[n]);
            const int h = n >> 6, d = n & 63;
            C[(((size_t)(batch * N_HEADS + h) * L_SEQ) + l) * DEPTH + d] = v;
        }
    }
}

// ---------------------------------------------------------------------------
// Output projection GEMM: C[4096,1024] = A @ B + bias, row-major out.
// ---------------------------------------------------------------------------
__global__ __launch_bounds__(256) void out_gemm(
    const float* __restrict__ A, const float* __restrict__ B,
    const float* __restrict__ bias, float* __restrict__ C)
{
    __shared__ float As[8][132];
    __shared__ float Bs[8][132];

    const int tid = threadIdx.x;
    const int bx = blockIdx.x;
    const int by = blockIdx.y;
    const int tx = tid & 15;
    const int ty = tid >> 4;

    const int aRow = tid >> 1;
    const int aCol = (tid & 1) << 2;
    const int bRow = tid >> 5;
    const int bCol = (tid & 31) << 2;

    const float* Ap = A + (size_t)(by * 128 + aRow) * 1024 + aCol;
    const float* Bp = B + (size_t)bRow * 1024 + bx * 128 + bCol;

    float acc[8][8];
#pragma unroll
    for (int i = 0; i < 8; i++)
#pragma unroll
        for (int j = 0; j < 8; j++) acc[i][j] = 0.f;

    for (int k0 = 0; k0 < 1024; k0 += 8) {
        float4 av = *(const float4*)(Ap + k0);
        float4 bv4 = *(const float4*)(Bp + (size_t)k0 * 1024);
        As[aCol + 0][aRow] = av.x;
        As[aCol + 1][aRow] = av.y;
        As[aCol + 2][aRow] = av.z;
        As[aCol + 3][aRow] = av.w;
        *(float4*)&Bs[bRow][bCol] = bv4;
        __syncthreads();

#pragma unroll
        for (int k = 0; k < 8; k++) {
            float a[8], b[8];
#pragma unroll
            for (int i = 0; i < 8; i++) a[i] = As[k][ty * 8 + i];
#pragma unroll
            for (int j = 0; j < 8; j++) b[j] = Bs[k][tx * 8 + j];
#pragma unroll
            for (int i = 0; i < 8; i++)
#pragma unroll
                for (int j = 0; j < 8; j++) acc[i][j] += a[i] * b[j];
        }
        __syncthreads();
    }

    const int m0 = by * 128 + ty * 8;
    const int n0 = bx * 128 + tx * 8;
#pragma unroll
    for (int i = 0; i < 8; i++) {
        const int m = m0 + i;
#pragma unroll
        for (int j = 0; j < 8; j++) {
            const int n = n0 + j;
            C[(size_t)m * DMODEL + n] = acc[i][j] + __ldg(&bias[n]);
        }
    }
}

// ---------------------------------------------------------------------------
// Fused causal attention with relative-position (skewed) bias.
//   logits[i,j] = (q_i.k_j + q_i.e[1023-i+j]) / 8    (j <= i), else -inf
//   where e = pos_emb[1024:] (rows 1024..2047).
// grid: (16 q-tiles, 64 batch*head), 256 threads, 64x64 tiles, online softmax.
// ---------------------------------------------------------------------------
__global__ __launch_bounds__(256) void attn_kernel(
    const float* __restrict__ Qg, const float* __restrict__ Kg,
    const float* __restrict__ Vg, const float* __restrict__ pe,
    float* __restrict__ ctx)
{
    extern __shared__ float sm[];
    float* Qs = sm;                 // [64][65]  Qs[d][r]
    float* Ks = Qs + 64 * 65;       // [64][65]  Ks[d][c]
    float* Vs = Ks + 64 * 65;       // [64][65]  Vs[j][c]
    float* Es = Vs + 64 * 65;       // [64][129] Es[d][er]
    float* Ss = Es + 64 * 129;      // [64][65]  Ss[r][j]
    float* rmax = Ss + 64 * 65;
    float* rsum = rmax + 64;
    float* ralp = rsum + 64;

    const int tid = threadIdx.x;
    const int qt = blockIdx.x;
    const int head = blockIdx.y;
    const int q0 = qt * 64;
    const size_t hb = (size_t)head * L_SEQ * DEPTH;
    const float* Qp = Qg + hb;
    const float* Kp = Kg + hb;
    const float* Vp = Vg + hb;

    const int tx = tid & 15, ty = tid >> 4;
    const int r0 = ty * 4, c0 = tx * 4;

    for (int idx = tid; idx < 64 * 64; idx += 256) {
        int r = idx >> 6, d = idx & 63;
        Qs[d * 65 + r] = Qp[(q0 + r) * 64 + d];
    }
    if (tid < 64) { rmax[tid] = -INFINITY; rsum[tid] = 0.f; }

    float acc[4][4];
#pragma unroll
    for (int i = 0; i < 4; i++)
#pragma unroll
        for (int j = 0; j < 4; j++) acc[i][j] = 0.f;

    for (int kt = 0; kt <= qt; kt++) {
        const int j0 = kt * 64;
        const int m0 = 960 - q0 + j0;   // >= 0 always (j0 <= q0)
        __syncthreads();                // protect Vs/Ss from previous iteration

        for (int idx = tid; idx < 64 * 64; idx += 256) {
            int c = idx >> 6, d = idx & 63;
            Ks[d * 65 + c] = Kp[(j0 + c) * 64 + d];
        }
        for (int idx = tid; idx < 64 * 64; idx += 256) {
            int j = idx >> 6, c = idx & 63;
            Vs[j * 65 + c] = Vp[(j0 + j) * 64 + c];
        }
        for (int idx = tid; idx < 128 * 64; idx += 256) {
            int er = idx >> 6, d = idx & 63;
            int m = m0 + er;
            Es[d * 129 + er] = (m < 1024) ? pe[(size_t)(1024 + m) * 64 + d] : 0.f;
        }
        __syncthreads();

        // S tile: logits = (q.k + q.e)/8, causal mask
        float sacc[4][4];
#pragma unroll
        for (int i = 0; i < 4; i++)
#pragma unroll
            for (int j = 0; j < 4; j++) sacc[i][j] = 0.f;

        const int eb = 60 - r0 + c0;   // er = eb + (j - i + 3) = 63 - r + c
#pragma unroll 4
        for (int d = 0; d < 64; d++) {
            float qv[4], kv[4], ev[7];
#pragma unroll
            for (int i = 0; i < 4; i++) qv[i] = Qs[d * 65 + r0 + i];
#pragma unroll
            for (int j = 0; j < 4; j++) kv[j] = Ks[d * 65 + c0 + j];
#pragma unroll
            for (int t = 0; t < 7; t++) ev[t] = Es[d * 129 + eb + t];
#pragma unroll
            for (int i = 0; i < 4; i++)
#pragma unroll
                for (int j = 0; j < 4; j++)
                    sacc[i][j] += qv[i] * (kv[j] + ev[j - i + 3]);
        }

#pragma unroll
        for (int i = 0; i < 4; i++)
#pragma unroll
            for (int j = 0; j < 4; j++) {
                int gi = q0 + r0 + i, gj = j0 + c0 + j;
                float v = sacc[i][j] * 0.125f;
                if (gj > gi) v = -1e30f;
                Ss[(r0 + i) * 65 + (c0 + j)] = v;
            }
        __syncthreads();

        // online softmax row phase
        if (tid < 64) {
            const int r = tid;
            float mold = rmax[r];
            float mx = mold;
            for (int j = 0; j < 64; j++) mx = fmaxf(mx, Ss[r * 65 + j]);
            float al = __expf(mold - mx);
            float s = 0.f;
            for (int j = 0; j < 64; j++) {
                float p = __expf(Ss[r * 65 + j] - mx);
                Ss[r * 65 + j] = p;
                s += p;
            }
            rsum[r] = rsum[r] * al + s;
            rmax[r] = mx;
            ralp[r] = al;
        }
        __syncthreads();

        // O = O*alpha + P @ V
        float al_i[4];
#pragma unroll
        for (int i = 0; i < 4; i++) al_i[i] = ralp[r0 + i];
#pragma unroll
        for (int i = 0; i < 4; i++)
#pragma unroll
            for (int j = 0; j < 4; j++) acc[i][j] *= al_i[i];

        for (int jj = 0; jj < 64; jj++) {
            float p[4], v[4];
#pragma unroll
            for (int i = 0; i < 4; i++) p[i] = Ss[(r0 + i) * 65 + jj];
#pragma unroll
            for (int j = 0; j < 4; j++) v[j] = Vs[jj * 65 + (c0 + j)];
#pragma unroll
            for (int i = 0; i < 4; i++)
#pragma unroll
                for (int j = 0; j < 4; j++) acc[i][j] += p[i] * v[j];
        }
    }

    // normalize + write ctx in [n][l][h*64+d] layout (ready for out-proj GEMM)
    const int n = head >> 4, h = head & 15;
#pragma unroll
    for (int i = 0; i < 4; i++) {
        const float inv = 1.0f / rsum[r0 + i];
        const int l = q0 + r0 + i;
#pragma unroll
        for (int j = 0; j < 4; j++) {
            const int d = c0 + j;
            ctx[(size_t)(n * L_SEQ + l) * DMODEL + h * 64 + d] = acc[i][j] * inv;
        }
    }
}

// ---------------------------------------------------------------------------
extern "C" void kernel_launch(void* const* d_in, const int* in_sizes, int n_in,
                              void* d_out, int out_size)
{
    (void)in_sizes; (void)n_in; (void)out_size;
    const float* q_in = (const float*)d_in[0];
    const float* k_in = (const float*)d_in[1];
    const float* v_in = (const float*)d_in[2];
    // d_in[3] = mask (known causal triu; handled analytically)
    const float* Wq = (const float*)d_in[4];
    const float* bq = (const float*)d_in[5];
    const float* Wk = (const float*)d_in[6];
    const float* bk = (const float*)d_in[7];
    const float* Wv = (const float*)d_in[8];
    const float* bv = (const float*)d_in[9];
    const float* Wo = (const float*)d_in[10];
    const float* bo = (const float*)d_in[11];
    const float* pe = (const float*)d_in[12];

    float *Qg, *Kg, *Vg, *Cg;
    cudaGetSymbolAddress((void**)&Qg, g_Q);
    cudaGetSymbolAddress((void**)&Kg, g_K);
    cudaGetSymbolAddress((void**)&Vg, g_V);
    cudaGetSymbolAddress((void**)&Cg, g_ctx);

    // Fused Q/K/V projections: one launch, 768 CTAs.
    qkv_gemm<<<dim3(8, 32, 3), 256>>>(q_in, k_in, v_in,
                                      Wq, Wk, Wv,
                                      bq, bk, bv,
                                      Qg, Kg, Vg);

    const int smem = (3 * 64 * 65 + 64 * 129 + 64 * 65 + 192) * (int)sizeof(float);
    cudaFuncSetAttribute(attn_kernel,
                         cudaFuncAttributeMaxDynamicSharedMemorySize, smem);
    attn_kernel<<<dim3(16, 64), 256, smem>>>(Qg, Kg, Vg, pe, Cg);

    out_gemm<<<dim3(8, 32), 256>>>(Cg, Wo, bo, (float*)d_out);
}

// round 12
// speedup vs baseline: 2.0714x; 2.0714x over previous
#include <cuda_runtime.h>
#include <math.h>
#include <stdint.h>

#define L_SEQ   1024
#define DMODEL  1024
#define N_BATCH 4
#define N_HEADS 16
#define DEPTH   64
#define M_TOT   (N_BATCH * L_SEQ)   // 4096

// Scratch (device globals: no allocation allowed)
__device__ float g_Q[N_BATCH * N_HEADS * L_SEQ * DEPTH];   // [n][h][l][d]
__device__ float g_K[N_BATCH * N_HEADS * L_SEQ * DEPTH];
__device__ float g_V[N_BATCH * N_HEADS * L_SEQ * DEPTH];
__device__ float g_ctx[M_TOT * DMODEL];                    // [n*L + l][h*64+d]

// ---------------------------------------------------------------------------
// TF32 tensor-core GEMM: C[4096,1024] = A[4096,1024] @ B[1024,1024] + bias
// 128x128x32 CTA tile, 256 threads (8 warps of 64x32), mma.m16n8k8.tf32.
// Double-buffered smem, 1 syncthreads per K-iter.
// ---------------------------------------------------------------------------
#define AS_STRIDE 36                  // 32 + 4 pad (m-major A)
#define BS_STRIDE 136                 // 128 + 8 pad (k-major B)
#define AS_SIZE   (128 * AS_STRIDE)   // 4608 floats
#define BS_SIZE   (32 * BS_STRIDE)    // 4352 floats
#define GEMM_SMEM_BYTES ((2 * AS_SIZE + 2 * BS_SIZE) * 4)   // 71680

__device__ __forceinline__ float to_tf32(float x) {
    float y;
    asm("cvt.rna.tf32.f32 %0, %1;" : "=f"(y) : "f"(x));
    return y;
}

__device__ __forceinline__ void mma_tf32(float d[4], const uint32_t a[4],
                                         const uint32_t b[2]) {
    asm volatile(
        "mma.sync.aligned.m16n8k8.row.col.f32.tf32.tf32.f32 "
        "{%0,%1,%2,%3}, {%4,%5,%6,%7}, {%8,%9}, {%0,%1,%2,%3};\n"
        : "+f"(d[0]), "+f"(d[1]), "+f"(d[2]), "+f"(d[3])
        : "r"(a[0]), "r"(a[1]), "r"(a[2]), "r"(a[3]), "r"(b[0]), "r"(b[1]));
}

// Mainloop: accumulate full K=1024 into acc[4][4][4].
__device__ __forceinline__ void gemm_mainloop(
    const float* __restrict__ A, const float* __restrict__ B,
    float* __restrict__ As, float* __restrict__ Bs,
    float acc[4][4][4], int bx, int by)
{
    const int tid = threadIdx.x;
    const int lane = tid & 31, wid = tid >> 5;
    const int g = lane >> 2, c = lane & 3;
    const int warp_m = wid >> 2, warp_n = wid & 3;

    const int arow = tid >> 3;          // + i*32
    const int acol = (tid & 7) * 4;
    const int brow = tid >> 5;          // + i*8
    const int bcol = (tid & 31) * 4;

    const float* Aptr = A + (size_t)(by * 128 + arow) * 1024 + acol;
    const float* Bptr = B + (size_t)brow * 1024 + bx * 128 + bcol;

    float4 areg[4], breg[4];
#pragma unroll
    for (int i = 0; i < 4; i++) {
        areg[i] = *(const float4*)(Aptr + (size_t)i * 32 * 1024);
        breg[i] = *(const float4*)(Bptr + (size_t)i * 8 * 1024);
    }

    int buf = 0;
    for (int k0 = 0; k0 < 1024; k0 += 32) {
        float* Ab = As + buf * AS_SIZE;
        float* Bb = Bs + buf * BS_SIZE;

        // store staged tiles (with tf32 rounding)
#pragma unroll
        for (int i = 0; i < 4; i++) {
            float4 v = areg[i];
            float4 w;
            w.x = to_tf32(v.x); w.y = to_tf32(v.y);
            w.z = to_tf32(v.z); w.w = to_tf32(v.w);
            *(float4*)(Ab + (arow + i * 32) * AS_STRIDE + acol) = w;
            v = breg[i];
            w.x = to_tf32(v.x); w.y = to_tf32(v.y);
            w.z = to_tf32(v.z); w.w = to_tf32(v.w);
            *(float4*)(Bb + (brow + i * 8) * BS_STRIDE + bcol) = w;
        }
        __syncthreads();

        // prefetch next K-slab (overlaps with compute below)
        if (k0 + 32 < 1024) {
#pragma unroll
            for (int i = 0; i < 4; i++) {
                areg[i] = *(const float4*)(Aptr + k0 + 32 + (size_t)i * 32 * 1024);
                breg[i] = *(const float4*)(Bptr + (size_t)(k0 + 32 + i * 8) * 1024);
            }
        }

        // compute 4 k-steps of 8
#pragma unroll
        for (int ks = 0; ks < 32; ks += 8) {
            uint32_t a[4][4], b[4][2];
#pragma unroll
            for (int mi = 0; mi < 4; mi++) {
                const float* ap = Ab + (warp_m * 64 + mi * 16 + g) * AS_STRIDE + ks + c;
                a[mi][0] = __float_as_uint(ap[0]);
                a[mi][1] = __float_as_uint(ap[8 * AS_STRIDE]);
                a[mi][2] = __float_as_uint(ap[4]);
                a[mi][3] = __float_as_uint(ap[8 * AS_STRIDE + 4]);
            }
#pragma unroll
            for (int ni = 0; ni < 4; ni++) {
                const float* bp = Bb + (ks + c) * BS_STRIDE + warp_n * 32 + ni * 8 + g;
                b[ni][0] = __float_as_uint(bp[0]);
                b[ni][1] = __float_as_uint(bp[4 * BS_STRIDE]);
            }
#pragma unroll
            for (int mi = 0; mi < 4; mi++)
#pragma unroll
                for (int ni = 0; ni < 4; ni++)
                    mma_tf32(acc[mi][ni], a[mi], b[ni]);
        }
        buf ^= 1;
    }
}

// Fused QKV projection (z selects Q/K/V), split-head output layout.
__global__ __launch_bounds__(256) void qkv_gemm_tf32(
    const float* __restrict__ Aq, const float* __restrict__ Ak,
    const float* __restrict__ Av,
    const float* __restrict__ Bq, const float* __restrict__ Bk,
    const float* __restrict__ Bv,
    const float* __restrict__ bqp, const float* __restrict__ bkp,
    const float* __restrict__ bvp,
    float* __restrict__ Cq, float* __restrict__ Ck, float* __restrict__ Cv)
{
    extern __shared__ float gsm[];
    float* As = gsm;
    float* Bs = gsm + 2 * AS_SIZE;

    const int z = blockIdx.z;
    const float* A    = (z == 0) ? Aq : (z == 1) ? Ak : Av;
    const float* B    = (z == 0) ? Bq : (z == 1) ? Bk : Bv;
    const float* bias = (z == 0) ? bqp : (z == 1) ? bkp : bvp;
    float*       C    = (z == 0) ? Cq : (z == 1) ? Ck : Cv;

    float acc[4][4][4];
#pragma unroll
    for (int mi = 0; mi < 4; mi++)
#pragma unroll
        for (int ni = 0; ni < 4; ni++)
#pragma unroll
            for (int t = 0; t < 4; t++) acc[mi][ni][t] = 0.f;

    gemm_mainloop(A, B, As, Bs, acc, blockIdx.x, blockIdx.y);

    const int lane = threadIdx.x & 31, wid = threadIdx.x >> 5;
    const int g = lane >> 2, c = lane & 3;
    const int m_base = blockIdx.y * 128 + (wid >> 2) * 64;
    const int n_base = blockIdx.x * 128 + (wid & 3) * 32;

#pragma unroll
    for (int mi = 0; mi < 4; mi++) {
#pragma unroll
        for (int ni = 0; ni < 4; ni++) {
            const int col = n_base + ni * 8 + 2 * c;
            const float b0 = __ldg(&bias[col]), b1 = __ldg(&bias[col + 1]);
            const int h = col >> 6, d = col & 63;
#pragma unroll
            for (int rr = 0; rr < 2; rr++) {
                const int r = m_base + mi * 16 + g + rr * 8;
                const int batch = r >> 10, l = r & 1023;
                float2 v;
                v.x = acc[mi][ni][rr * 2 + 0] + b0;
                v.y = acc[mi][ni][rr * 2 + 1] + b1;
                *(float2*)&C[(((size_t)(batch * N_HEADS + h) * L_SEQ) + l) * DEPTH + d] = v;
            }
        }
    }
}

// Output projection GEMM, row-major output.
__global__ __launch_bounds__(256) void out_gemm_tf32(
    const float* __restrict__ A, const float* __restrict__ B,
    const float* __restrict__ bias, float* __restrict__ C)
{
    extern __shared__ float gsm[];
    float* As = gsm;
    float* Bs = gsm + 2 * AS_SIZE;

    float acc[4][4][4];
#pragma unroll
    for (int mi = 0; mi < 4; mi++)
#pragma unroll
        for (int ni = 0; ni < 4; ni++)
#pragma unroll
            for (int t = 0; t < 4; t++) acc[mi][ni][t] = 0.f;

    gemm_mainloop(A, B, As, Bs, acc, blockIdx.x, blockIdx.y);

    const int lane = threadIdx.x & 31, wid = threadIdx.x >> 5;
    const int g = lane >> 2, c = lane & 3;
    const int m_base = blockIdx.y * 128 + (wid >> 2) * 64;
    const int n_base = blockIdx.x * 128 + (wid & 3) * 32;

#pragma unroll
    for (int mi = 0; mi < 4; mi++) {
#pragma unroll
        for (int ni = 0; ni < 4; ni++) {
            const int col = n_base + ni * 8 + 2 * c;
            const float b0 = __ldg(&bias[col]), b1 = __ldg(&bias[col + 1]);
#pragma unroll
            for (int rr = 0; rr < 2; rr++) {
                const int r = m_base + mi * 16 + g + rr * 8;
                float2 v;
                v.x = acc[mi][ni][rr * 2 + 0] + b0;
                v.y = acc[mi][ni][rr * 2 + 1] + b1;
                *(float2*)&C[(size_t)r * DMODEL + col] = v;
            }
        }
    }
}

// ---------------------------------------------------------------------------
// Fused causal attention with relative-position (skewed) bias.
//   logits[i,j] = (q_i.k_j + q_i.e[1023-i+j]) / 8    (j <= i), else -inf
// Parallel softmax (4 thr/row); float4 QK, E-bias and PV loops (4-aligned
// strides). All FFMA accumulation orders identical to the scalar version.
// ---------------------------------------------------------------------------
#define QS_STRIDE 68
#define KS_STRIDE 68
#define VS_STRIDE 68
#define SS_STRIDE 68
#define ES_STRIDE 132

__global__ __launch_bounds__(256) void attn_kernel(
    const float* __restrict__ Qg, const float* __restrict__ Kg,
    const float* __restrict__ Vg, const float* __restrict__ pe,
    float* __restrict__ ctx)
{
    extern __shared__ float sm[];
    float* Qs = sm;                       // [64][68]  Qs[d][r]
    float* Ks = Qs + 64 * QS_STRIDE;      // [64][68]  Ks[d][c]
    float* Vs = Ks + 64 * KS_STRIDE;      // [64][68]  Vs[j][c]
    float* Es = Vs + 64 * VS_STRIDE;      // [64][132] Es[d][er], er<128
    float* Ss = Es + 64 * ES_STRIDE;      // [64][68]  Ss[r][j]
    float* rmax = Ss + 64 * SS_STRIDE;
    float* rsum = rmax + 64;
    float* ralp = rsum + 64;

    const int tid = threadIdx.x;
    const int qt = blockIdx.x;
    const int head = blockIdx.y;
    const int q0 = qt * 64;
    const size_t hb = (size_t)head * L_SEQ * DEPTH;
    const float* Qp = Qg + hb;
    const float* Kp = Kg + hb;
    const float* Vp = Vg + hb;

    const int tx = tid & 15, ty = tid >> 4;
    const int r0 = ty * 4, c0 = tx * 4;

    for (int idx = tid; idx < 64 * 64; idx += 256) {
        int r = idx >> 6, d = idx & 63;
        Qs[d * QS_STRIDE + r] = Qp[(q0 + r) * 64 + d];
    }
    if (tid < 64) { rmax[tid] = -INFINITY; rsum[tid] = 0.f; }

    float acc[4][4];
#pragma unroll
    for (int i = 0; i < 4; i++)
#pragma unroll
        for (int j = 0; j < 4; j++) acc[i][j] = 0.f;

    for (int kt = 0; kt <= qt; kt++) {
        const int j0 = kt * 64;
        const int m0 = 960 - q0 + j0;   // >= 0 always (j0 <= q0)
        __syncthreads();                // protect Vs/Ss from previous iteration

        for (int idx = tid; idx < 64 * 64; idx += 256) {
            int cc = idx >> 6, d = idx & 63;
            Ks[d * KS_STRIDE + cc] = Kp[(j0 + cc) * 64 + d];
        }
        for (int idx = tid; idx < 64 * 64; idx += 256) {
            int j = idx >> 6, cc = idx & 63;
            Vs[j * VS_STRIDE + cc] = Vp[(j0 + j) * 64 + cc];
        }
        for (int idx = tid; idx < 128 * 64; idx += 256) {
            int er = idx >> 6, d = idx & 63;
            int m = m0 + er;
            Es[d * ES_STRIDE + er] = (m < 1024) ? pe[(size_t)(1024 + m) * 64 + d] : 0.f;
        }
        __syncthreads();

        float sacc[4][4];
#pragma unroll
        for (int i = 0; i < 4; i++)
#pragma unroll
            for (int j = 0; j < 4; j++) sacc[i][j] = 0.f;

        const int eb = 60 - r0 + c0;   // multiple of 4; er = eb + (j-i+3)
#pragma unroll 4
        for (int d = 0; d < 64; d++) {
            const float4 qv4 = *(const float4*)&Qs[d * QS_STRIDE + r0];
            const float4 kv4 = *(const float4*)&Ks[d * KS_STRIDE + c0];
            const float4 e0  = *(const float4*)&Es[d * ES_STRIDE + eb];
            const float4 e1  = *(const float4*)&Es[d * ES_STRIDE + eb + 4];
            const float qv[4] = {qv4.x, qv4.y, qv4.z, qv4.w};
            const float kv[4] = {kv4.x, kv4.y, kv4.z, kv4.w};
            const float ev[8] = {e0.x, e0.y, e0.z, e0.w, e1.x, e1.y, e1.z, e1.w};
#pragma unroll
            for (int i = 0; i < 4; i++)
#pragma unroll
                for (int j = 0; j < 4; j++)
                    sacc[i][j] += qv[i] * (kv[j] + ev[j - i + 3]);
        }

#pragma unroll
        for (int i = 0; i < 4; i++)
#pragma unroll
            for (int j = 0; j < 4; j++) {
                int gi = q0 + r0 + i, gj = j0 + c0 + j;
                float v = sacc[i][j] * 0.125f;
                if (gj > gi) v = -1e30f;
                Ss[(r0 + i) * SS_STRIDE + (c0 + j)] = v;
            }
        __syncthreads();

        // online softmax row phase: 4 threads per row, shfl_xor reduce.
        {
            const int r = tid >> 2;          // 0..63
            const int sub = tid & 3;         // 0..3 (consecutive lanes)
            const float mold = rmax[r];
            float* row = Ss + r * SS_STRIDE + sub * 16;

            float mx = -INFINITY;
#pragma unroll
            for (int j = 0; j < 16; j++) mx = fmaxf(mx, row[j]);
            mx = fmaxf(mx, __shfl_xor_sync(0xffffffffu, mx, 1));
            mx = fmaxf(mx, __shfl_xor_sync(0xffffffffu, mx, 2));
            mx = fmaxf(mx, mold);

            float s = 0.f;
#pragma unroll
            for (int j = 0; j < 16; j++) {
                float p = __expf(row[j] - mx);
                row[j] = p;
                s += p;
            }
            s += __shfl_xor_sync(0xffffffffu, s, 1);
            s += __shfl_xor_sync(0xffffffffu, s, 2);

            if (sub == 0) {
                const float al = __expf(mold - mx);
                rsum[r] = rsum[r] * al + s;
                rmax[r] = mx;
                ralp[r] = al;
            }
        }
        __syncthreads();

        float al_i[4];
#pragma unroll
        for (int i = 0; i < 4; i++) al_i[i] = ralp[r0 + i];
#pragma unroll
        for (int i = 0; i < 4; i++)
#pragma unroll
            for (int j = 0; j < 4; j++) acc[i][j] *= al_i[i];

        // O += P @ V, float4 smem loads, 4 jj per iteration.
        for (int jj = 0; jj < 64; jj += 4) {
            float4 p4[4], v4[4];
#pragma unroll
            for (int i = 0; i < 4; i++)
                p4[i] = *(const float4*)&Ss[(r0 + i) * SS_STRIDE + jj];
#pragma unroll
            for (int t = 0; t < 4; t++)
                v4[t] = *(const float4*)&Vs[(jj + t) * VS_STRIDE + c0];
#pragma unroll
            for (int t = 0; t < 4; t++) {
                const float* vv = &v4[t].x;
#pragma unroll
                for (int i = 0; i < 4; i++) {
                    const float pi = (&p4[i].x)[t];
#pragma unroll
                    for (int j = 0; j < 4; j++)
                        acc[i][j] += pi * vv[j];
                }
            }
        }
    }

    const int n = head >> 4, h = head & 15;
#pragma unroll
    for (int i = 0; i < 4; i++) {
        const float inv = 1.0f / rsum[r0 + i];
        const int l = q0 + r0 + i;
#pragma unroll
        for (int j = 0; j < 4; j++) {
            const int d = c0 + j;
            ctx[(size_t)(n * L_SEQ + l) * DMODEL + h * 64 + d] = acc[i][j] * inv;
        }
    }
}

#define ATTN_SMEM_BYTES ((64 * QS_STRIDE + 64 * KS_STRIDE + 64 * VS_STRIDE + \
                          64 * ES_STRIDE + 64 * SS_STRIDE + 192) * (int)sizeof(float))

// ---------------------------------------------------------------------------
extern "C" void kernel_launch(void* const* d_in, const int* in_sizes, int n_in,
                              void* d_out, int out_size)
{
    (void)in_sizes; (void)n_in; (void)out_size;
    const float* q_in = (const float*)d_in[0];
    const float* k_in = (const float*)d_in[1];
    const float* v_in = (const float*)d_in[2];
    // d_in[3] = mask (known causal triu; handled analytically)
    const float* Wq = (const float*)d_in[4];
    const float* bq = (const float*)d_in[5];
    const float* Wk = (const float*)d_in[6];
    const float* bk = (const float*)d_in[7];
    const float* Wv = (const float*)d_in[8];
    const float* bv = (const float*)d_in[9];
    const float* Wo = (const float*)d_in[10];
    const float* bo = (const float*)d_in[11];
    const float* pe = (const float*)d_in[12];

    float *Qg, *Kg, *Vg, *Cg;
    cudaGetSymbolAddress((void**)&Qg, g_Q);
    cudaGetSymbolAddress((void**)&Kg, g_K);
    cudaGetSymbolAddress((void**)&Vg, g_V);
    cudaGetSymbolAddress((void**)&Cg, g_ctx);

    cudaFuncSetAttribute(qkv_gemm_tf32,
                         cudaFuncAttributeMaxDynamicSharedMemorySize, GEMM_SMEM_BYTES);
    cudaFuncSetAttribute(out_gemm_tf32,
                         cudaFuncAttributeMaxDynamicSharedMemorySize, GEMM_SMEM_BYTES);

    qkv_gemm_tf32<<<dim3(8, 32, 3), 256, GEMM_SMEM_BYTES>>>(
        q_in, k_in, v_in, Wq, Wk, Wv, bq, bk, bv, Qg, Kg, Vg);

    cudaFuncSetAttribute(attn_kernel,
                         cudaFuncAttributeMaxDynamicSharedMemorySize, ATTN_SMEM_BYTES);
    attn_kernel<<<dim3(16, 64), 256, ATTN_SMEM_BYTES>>>(Qg, Kg, Vg, pe, Cg);

    out_gemm_tf32<<<dim3(8, 32), 256, GEMM_SMEM_BYTES>>>(Cg, Wo, bo, (float*)d_out);
}